// round 1
// baseline (speedup 1.0000x reference)
#include <cuda_runtime.h>

// HebbianNet closed form:
//   z[b,o]  = sum_i v[b,i] * W[o,i]
//   vj      = relu(z + bias[o])
//   out     = vj + r*( A*S2[b] + Bc*z + C*vj*S1[b] + D*S1[b] )
// with A,Bc,C,D folded from cw1/cb1/cw2/cb2, r = RATE/batch_num,
// S1[b] = sum_i v[b,i], S2[b] = sum_i v[b,i]^2.
//
// Shapes fixed for this problem: B=8, K(in)=1024 for all three layers,
// O = 1024, 1024, 512.

#define B_DIM 8
#define K_DIM 1024
#define RATE_F 0.001f

// inter-layer activation scratch (allocation-free rule: __device__ globals)
__device__ float g_act1[B_DIM * K_DIM];
__device__ float g_act2[B_DIM * K_DIM];

__global__ __launch_bounds__(256, 1)
void hebbian_layer_kernel(const float* __restrict__ V,      // (8, 1024)
                          const float* __restrict__ W,      // (O, 1024)
                          const float* __restrict__ bias,   // (O,)
                          const float* __restrict__ cw1,    // (8, 3)
                          const float* __restrict__ cb1,    // (8,)
                          const float* __restrict__ cw2,    // (1, 8)
                          const float* __restrict__ cb2,    // (1,)
                          const int*   __restrict__ bn,     // scalar
                          float*       __restrict__ out,    // (8, O)
                          int O)
{
    __shared__ float Vs[B_DIM * K_DIM];   // 32 KB staged activations
    __shared__ float S1s[B_DIM], S2s[B_DIM];

    const int tid  = threadIdx.x;        // 0..255
    const int wid  = tid >> 5;           // warp 0..7
    const int lane = tid & 31;

    // ---- fold the 1x1 convs into 4 scalars (uniform loads, all threads) ----
    float A = 0.f, Bc = 0.f, C = 0.f, D = 0.f;
#pragma unroll
    for (int h = 0; h < 8; ++h) {
        float e = cw2[h];
        A  = fmaf(e, cw1[3*h + 0], A);
        Bc = fmaf(e, cw1[3*h + 1], Bc);
        C  = fmaf(e, cw1[3*h + 2], C);
        D  = fmaf(e, cb1[h],       D);
    }
    D += cb2[0];
    const float rr = RATE_F / (float)bn[0];

    // ---- stage v into shared memory (fully coalesced float4) ----
    const float4* V4  = (const float4*)V;
    float4*       Vs4 = (float4*)Vs;
#pragma unroll
    for (int m = 0; m < 8; ++m) {
        int i4 = tid + 256 * m;          // 2048 float4 total
        Vs4[i4] = V4[i4];
    }
    __syncthreads();

    // ---- per-batch stats: warp w handles batch b = w ----
    {
        float s1 = 0.f, s2 = 0.f;
#pragma unroll
        for (int m = 0; m < 8; ++m) {
            float4 v4 = Vs4[wid * 256 + m * 32 + lane];
            s1 += v4.x + v4.y + v4.z + v4.w;
            s2 = fmaf(v4.x, v4.x, s2);
            s2 = fmaf(v4.y, v4.y, s2);
            s2 = fmaf(v4.z, v4.z, s2);
            s2 = fmaf(v4.w, v4.w, s2);
        }
#pragma unroll
        for (int off = 16; off > 0; off >>= 1) {
            s1 += __shfl_xor_sync(0xffffffffu, s1, off);
            s2 += __shfl_xor_sync(0xffffffffu, s2, off);
        }
        if (lane == 0) { S1s[wid] = s1; S2s[wid] = s2; }
    }
    __syncthreads();

    // ---- main GEMV: warp wid owns output row o, lanes span K ----
    const int o = blockIdx.x * 8 + wid;
    const float4* Wr = (const float4*)(W + (size_t)o * K_DIM);

    float acc[B_DIM];
#pragma unroll
    for (int b = 0; b < B_DIM; ++b) acc[b] = 0.f;

#pragma unroll
    for (int m = 0; m < 8; ++m) {
        float4 w4 = Wr[m * 32 + lane];   // dense 512B per warp per load
#pragma unroll
        for (int b = 0; b < B_DIM; ++b) {
            float4 v4 = Vs4[b * 256 + m * 32 + lane];
            acc[b] = fmaf(w4.x, v4.x, acc[b]);
            acc[b] = fmaf(w4.y, v4.y, acc[b]);
            acc[b] = fmaf(w4.z, v4.z, acc[b]);
            acc[b] = fmaf(w4.w, v4.w, acc[b]);
        }
    }

    // butterfly reduce each batch accumulator across the warp
#pragma unroll
    for (int b = 0; b < B_DIM; ++b) {
#pragma unroll
        for (int off = 16; off > 0; off >>= 1)
            acc[b] += __shfl_xor_sync(0xffffffffu, acc[b], off);
    }

    if (lane == 0) {
        const float bo = bias[o];
#pragma unroll
        for (int b = 0; b < B_DIM; ++b) {
            float z  = acc[b];
            float vj = fmaxf(z + bo, 0.f);
            float sh = fmaf(A, S2s[b], fmaf(Bc, z, (C * vj + D) * S1s[b]));
            out[(size_t)b * O + o] = fmaf(rr, sh, vj);
        }
    }
}

extern "C" void kernel_launch(void* const* d_in, const int* in_sizes, int n_in,
                              void* d_out, int out_size)
{
    (void)in_sizes; (void)n_in; (void)out_size;
    const float* x   = (const float*)d_in[0];
    const float* W1  = (const float*)d_in[1];
    const float* b1  = (const float*)d_in[2];
    const float* W2  = (const float*)d_in[3];
    const float* b2  = (const float*)d_in[4];
    const float* W3  = (const float*)d_in[5];
    const float* b3  = (const float*)d_in[6];
    const float* cw1 = (const float*)d_in[7];
    const float* cb1 = (const float*)d_in[8];
    const float* cw2 = (const float*)d_in[9];
    const float* cb2 = (const float*)d_in[10];
    const int*   bn  = (const int*)d_in[11];
    float* outp = (float*)d_out;

    float *act1, *act2;
    cudaGetSymbolAddress((void**)&act1, g_act1);
    cudaGetSymbolAddress((void**)&act2, g_act2);

    // layer 1: (8,1024) -> (8,1024)
    hebbian_layer_kernel<<<1024 / 8, 256>>>(x,    W1, b1, cw1, cb1, cw2, cb2, bn, act1, 1024);
    // layer 2: (8,1024) -> (8,1024)
    hebbian_layer_kernel<<<1024 / 8, 256>>>(act1, W2, b2, cw1, cb1, cw2, cb2, bn, act2, 1024);
    // layer 3: (8,1024) -> (8,512)
    hebbian_layer_kernel<<<512 / 8,  256>>>(act2, W3, b3, cw1, cb1, cw2, cb2, bn, outp, 512);
}